// round 8
// baseline (speedup 1.0000x reference)
#include <cuda_runtime.h>
#include <cstdint>

#define BB 128
#define NN 16384
#define KK 32
#define CAP 4096                       // per-row candidate cap (bench needs ~100)
#define THR 2.5f                       // fast-path threshold
#define NBINS 4096                     // fallback histogram
#define TPB_F 256
#define BPT (NBINS / TPB_F)            // 16 bins per thread (fallback scan)

// Zero-fill kernel shape: 4096 CTAs x 256 thr x 16 float4 = 256 MB
#define TPB_Z 256
#define ZF4_PER_T 16
#define ZGRID (BB * NN * KK / 4 / (TPB_Z * ZF4_PER_T))   // 4096

// Chunk-collect shape: 8 chunks/row of 2048 elems, 256 thr x 8 elems
#define NCH 8
#define CHN (NN / NCH)                 // 2048

// eps = FLT_EPSILON = 2^-23 ; eps^2 = 2^-46 ; 1/eps^2 = 2^46 (exact powers of 2)
#define EPSf    1.1920929e-07f
#define E2f     1.4210854715202004e-14f
#define INV_E2f 7.0368744177664e13f

// Device scratch (allocation-free rule: __device__ globals; zero-initialized)
__device__ float    g_cand[BB * CAP];
__device__ unsigned g_cidx[BB * CAP];
__device__ unsigned g_cnt[BB];         // reset to 0 by finalize each launch

__device__ __forceinline__ unsigned key_of(float f) {
    unsigned u = __float_as_uint(f);
    return (u & 0x80000000u) ? ~u : (u | 0x80000000u);
}
__device__ __forceinline__ float key_to_float(unsigned k) {
    unsigned u = (k & 0x80000000u) ? (k & 0x7FFFFFFFu) : ~k;
    return __uint_as_float(u);
}

// ---------------------------------------------------------------------------
// chunk_collect: 1024 CTAs (8 per row) x 256 thr. Pure threshold filter into
// per-row global candidate lists via warp-aggregated global atomics.
// x >= THR is a provable superset of the exact top-32 and of every eps-window
// contributor whenever the row has >= 32 elements above THR (ulp(THR) > eps).
// ---------------------------------------------------------------------------
__global__ void __launch_bounds__(TPB_F) chunk_collect_kernel(const float* __restrict__ x) {
    const int cid  = blockIdx.x;           // b*8 + chunk
    const int b    = cid >> 3;
    const int tid  = threadIdx.x;
    const int lane = tid & 31;

    const float4* xr = (const float4*)(x) + (size_t)cid * (CHN / 4);
    const float4 v0 = xr[tid];
    const float4 v1 = xr[tid + TPB_F];
    float vals[8] = {v0.x, v0.y, v0.z, v0.w, v1.x, v1.y, v1.z, v1.w};
    const unsigned ibase = (unsigned)(cid & 7) * CHN;

    #pragma unroll
    for (int c = 0; c < 8; c++) {
        const bool pred = vals[c] >= THR;
        const unsigned bm = __ballot_sync(0xFFFFFFFFu, pred);
        if (bm) {
            const int leader = __ffs(bm) - 1;
            unsigned basep = 0;
            if (lane == leader) basep = atomicAdd(&g_cnt[b], (unsigned)__popc(bm));
            basep = __shfl_sync(0xFFFFFFFFu, basep, leader);
            if (pred) {
                const unsigned p = basep + (unsigned)__popc(bm & ((1u << lane) - 1u));
                if (p < CAP) {
                    const unsigned idx = ibase + 4u * (unsigned)(tid + (c >> 2) * TPB_F) + (c & 3);
                    g_cand[b * CAP + p] = vals[c];
                    g_cidx[b * CAP + p] = idx;
                }
            }
        }
    }
}

// ---------------------------------------------------------------------------
// zero_kernel: pure streaming zero-fill (measured ~6.5 TB/s). Every
// non-candidate output is exactly 0 (s_j >= 1 always -> relu(1-s_j) == 0).
// ---------------------------------------------------------------------------
__global__ void __launch_bounds__(TPB_Z) zero_kernel(float4* __restrict__ o) {
    const float4 z = make_float4(0.f, 0.f, 0.f, 0.f);
    float4* base = o + (size_t)blockIdx.x * (TPB_Z * ZF4_PER_T) + threadIdx.x;
    #pragma unroll
    for (int k = 0; k < ZF4_PER_T; k++)
        __stcs(base + k * TPB_Z, z);
}

// ---------------------------------------------------------------------------
// finalize_scatter: 128 CTAs (one per row) x 256 thr.
// Loads candidates (L2-hot), rank-selects exact top-32, computes c_j,
// scatter-writes each candidate's 32-wide output segment, resets g_cnt.
// Fallback (cnt < 32 or > CAP; never on bench data): exact 12-bit histogram
// re-select over the full row read from global.
// ---------------------------------------------------------------------------
__global__ void __launch_bounds__(TPB_F) finalize_scatter_kernel(const float* __restrict__ x,
                                                                 float* __restrict__ out) {
    extern __shared__ unsigned char smem_raw[];
    float*    cand = (float*)smem_raw;                       // 16 KB
    unsigned* cidx = (unsigned*)(smem_raw + CAP * 4);        // 16 KB
    unsigned* hist = (unsigned*)(smem_raw + CAP * 8);        // 16 KB (fallback)
    __shared__ unsigned csum[TPB_F];
    __shared__ float st[KK], sc[KK];
    __shared__ unsigned s_cnt;
    __shared__ int s_bin;

    const int b   = blockIdx.x;
    const int tid = threadIdx.x;

    unsigned cnt = g_cnt[b];
    if (tid == 0) g_cnt[b] = 0;          // reset for next graph replay

    if (cnt >= KK && cnt <= CAP) {
        // Fast path: copy candidates from global scratch (L2-hot, ~100 elems)
        for (unsigned i = tid; i < cnt; i += TPB_F) {
            cand[i] = g_cand[b * CAP + i];
            cidx[i] = g_cidx[b * CAP + i];
        }
        __syncthreads();
    } else {
        // ---- Exact fallback: 12-bit histogram select over the full row ----
        const float* xrow = x + (size_t)b * NN;
        for (int i = tid; i < NBINS; i += TPB_F) hist[i] = 0;
        if (tid == 0) s_cnt = 0;
        __syncthreads();
        for (int i = tid; i < NN; i += TPB_F) {
            unsigned dg = key_of(xrow[i]) >> 20;
            unsigned peers = __match_any_sync(0xFFFFFFFFu, dg);
            if ((tid & 31) == __ffs(peers) - 1)
                atomicAdd(&hist[dg], (unsigned)__popc(peers));
        }
        __syncthreads();
        {
            unsigned s = 0;
            #pragma unroll
            for (int j = 0; j < BPT; j++) s += hist[tid * BPT + j];
            csum[tid] = s;
            __syncthreads();
            #pragma unroll
            for (int off = 1; off < TPB_F; off <<= 1) {
                unsigned t = (tid + off < TPB_F) ? csum[tid + off] : 0u;
                __syncthreads();
                csum[tid] += t;
                __syncthreads();
            }
        }
        {
            unsigned incl = csum[tid];
            unsigned excl = (tid < TPB_F - 1) ? csum[tid + 1] : 0u;
            if (incl >= KK && excl < KK) {
                unsigned cum = excl;
                #pragma unroll
                for (int j = BPT - 1; j >= 0; j--) {
                    cum += hist[tid * BPT + j];
                    if (cum >= KK) { s_bin = tid * BPT + j; break; }
                }
            }
        }
        __syncthreads();
        const float binlo   = key_to_float((unsigned)s_bin << 20);
        const unsigned thrk = key_of(binlo - 2.0f * EPSf);
        for (int i = tid; i < NN; i += TPB_F) {
            float v = xrow[i];
            if (key_of(v) >= thrk) {
                unsigned p = atomicAdd(&s_cnt, 1u);
                if (p < CAP) { cand[p] = v; cidx[p] = (unsigned)i; }
            }
        }
        __syncthreads();
        cnt = min(s_cnt, (unsigned)CAP);
    }
    const int m = (int)cnt;

    // ---- Rank-select top-32 (descending) among m candidates ----
    for (int i0 = tid; i0 < m; i0 += TPB_F) {
        unsigned kv = key_of(cand[i0]);
        int rank = 0;
        for (int i = 0; i < m; i++) {
            unsigned kw = key_of(cand[i]);
            rank += (kw > kv) || (kw == kv && i < i0);
        }
        if (rank < KK) st[rank] = cand[i0];
    }
    __syncthreads();

    // ---- c_j = 1 - x_m_sum_j (terms are exactly 0 or 1 on the fast path ->
    // order-invariant despite atomic collection order) ----
    if (tid < KK) {
        const float tj = st[tid];
        float acc = 0.f;
        for (int i = 0; i < m; i++) {
            float d = cand[i] - tj;
            acc += fmaxf(__fmaf_rn(-d, d, E2f), 0.f) * INV_E2f;
        }
        sc[tid] = 1.0f - acc;
    }
    __syncthreads();

    // ---- Scatter: rewrite the 32-wide segment of each candidate position ----
    for (int w = tid; w < m * 8; w += TPB_F) {
        const int p = w >> 3, q = w & 7, j0 = q * 4;
        const float xv     = cand[p];
        const unsigned idx = cidx[p];
        float d;
        float4 r;
        d = xv - st[j0 + 0]; r.x = fmaxf(__fmaf_rn(fmaxf(__fmaf_rn(-d, d, E2f), 0.f), INV_E2f, sc[j0 + 0]), 0.f);
        d = xv - st[j0 + 1]; r.y = fmaxf(__fmaf_rn(fmaxf(__fmaf_rn(-d, d, E2f), 0.f), INV_E2f, sc[j0 + 1]), 0.f);
        d = xv - st[j0 + 2]; r.z = fmaxf(__fmaf_rn(fmaxf(__fmaf_rn(-d, d, E2f), 0.f), INV_E2f, sc[j0 + 2]), 0.f);
        d = xv - st[j0 + 3]; r.w = fmaxf(__fmaf_rn(fmaxf(__fmaf_rn(-d, d, E2f), 0.f), INV_E2f, sc[j0 + 3]), 0.f);
        float4* dst = (float4*)(out + ((size_t)b * NN + idx) * KK);
        dst[q] = r;
    }
}

// ---------------------------------------------------------------------------
extern "C" void kernel_launch(void* const* d_in, const int* in_sizes, int n_in,
                              void* d_out, int out_size) {
    const float* x = (const float*)d_in[0];
    float* out = (float*)d_out;
    (void)in_sizes; (void)n_in; (void)out_size;   // shapes fixed: (128,16384), k=32

    const int smem_f = CAP * 8 + NBINS * 4;       // 48 KB (cand | cidx | hist)
    cudaFuncSetAttribute(finalize_scatter_kernel,
                         cudaFuncAttributeMaxDynamicSharedMemorySize, smem_f);

    chunk_collect_kernel<<<BB * NCH, TPB_F>>>(x);
    zero_kernel<<<ZGRID, TPB_Z>>>((float4*)out);
    finalize_scatter_kernel<<<BB, TPB_F, smem_f>>>(x, out);
}

// round 9
// speedup vs baseline: 1.1516x; 1.1516x over previous
#include <cuda_runtime.h>
#include <cstdint>

#define BB 128
#define NN 16384
#define KK 32
#define CAP 4096                       // per-row candidate cap (bench needs ~100)
#define THR 2.5f                       // fast-path threshold
#define NBINS 4096                     // fallback histogram
#define TPB_F 256
#define BPT (NBINS / TPB_F)            // 16 bins per thread (fallback scan)

// zero_collect shape: 4096 CTAs (32 per row), 256 thr.
// Each CTA: zeroes 512 output segments (64 KB) + filters the matching 512 x's.
#define TPB_Z 256
#define ZSEG 512                       // n-positions per CTA
#define ZGRID (BB * (NN / ZSEG))       // 4096
#define ZF4_PER_T (ZSEG * KK / 4 / TPB_Z)  // 16 float4 stores per thread

// eps = FLT_EPSILON = 2^-23 ; eps^2 = 2^-46 ; 1/eps^2 = 2^46 (exact powers of 2)
#define EPSf    1.1920929e-07f
#define E2f     1.4210854715202004e-14f
#define INV_E2f 7.0368744177664e13f

// Device scratch (allocation-free rule: __device__ globals; zero-initialized)
__device__ float    g_cand[BB * CAP];
__device__ unsigned g_cidx[BB * CAP];
__device__ unsigned g_cnt[BB];         // reset to 0 by finalize each launch

__device__ __forceinline__ unsigned key_of(float f) {
    unsigned u = __float_as_uint(f);
    return (u & 0x80000000u) ? ~u : (u | 0x80000000u);
}
__device__ __forceinline__ float key_to_float(unsigned k) {
    unsigned u = (k & 0x80000000u) ? (k & 0x7FFFFFFFu) : ~k;
    return __uint_as_float(u);
}

// ---------------------------------------------------------------------------
// zero_collect: streaming zero-fill of the output (exact for all
// non-candidate positions, since s_j >= 1 -> relu(1-s_j) == 0) FUSED with the
// threshold collect of the x-range this CTA's output segment corresponds to.
// The 2 KB x-read rides along with the 64 KB store stream (+3% traffic).
// ---------------------------------------------------------------------------
__global__ void __launch_bounds__(TPB_Z) zero_collect_kernel(const float* __restrict__ x,
                                                             float4* __restrict__ out) {
    const int cid  = blockIdx.x;              // b*32 + seg
    const int b    = cid >> 5;
    const int n0   = (cid & 31) * ZSEG;
    const int tid  = threadIdx.x;
    const int lane = tid & 31;

    // Issue the x loads first (2 floats/thread, coalesced), hide under stores.
    const float2 xv = ((const float2*)(x + (size_t)b * NN + n0))[tid];

    // Zero the 64 KB output slab of this segment.
    const float4 z = make_float4(0.f, 0.f, 0.f, 0.f);
    float4* basep = out + ((size_t)b * NN + n0) * (KK / 4) + tid;
    #pragma unroll
    for (int k = 0; k < ZF4_PER_T; k++)
        __stcs(basep + k * TPB_Z, z);

    // Threshold collect (x >= THR: provable superset of the exact top-32 and
    // of every eps-window contributor when >=32 elements clear THR, since
    // ulp(THR) > eps). Ballot-aggregated global atomic append.
    float vals[2] = {xv.x, xv.y};
    #pragma unroll
    for (int c = 0; c < 2; c++) {
        const bool pred = vals[c] >= THR;
        const unsigned bm = __ballot_sync(0xFFFFFFFFu, pred);
        if (bm) {
            const int leader = __ffs(bm) - 1;
            unsigned basec = 0;
            if (lane == leader) basec = atomicAdd(&g_cnt[b], (unsigned)__popc(bm));
            basec = __shfl_sync(0xFFFFFFFFu, basec, leader);
            if (pred) {
                const unsigned p = basec + (unsigned)__popc(bm & ((1u << lane) - 1u));
                if (p < CAP) {
                    g_cand[b * CAP + p] = vals[c];
                    g_cidx[b * CAP + p] = (unsigned)(n0 + 2 * tid + c);
                }
            }
        }
    }
}

// ---------------------------------------------------------------------------
// finalize_scatter: 128 CTAs (one per row) x 256 thr.
// Loads candidates (L2-hot), rank-selects exact top-32, computes c_j,
// scatter-writes each candidate's 32-wide output segment, resets g_cnt.
// Fallback (cnt < 32 or > CAP; never on bench data): exact 12-bit histogram
// re-select over the full row read from global.
// ---------------------------------------------------------------------------
__global__ void __launch_bounds__(TPB_F) finalize_scatter_kernel(const float* __restrict__ x,
                                                                 float* __restrict__ out) {
    extern __shared__ unsigned char smem_raw[];
    float*    cand = (float*)smem_raw;                       // 16 KB
    unsigned* cidx = (unsigned*)(smem_raw + CAP * 4);        // 16 KB
    unsigned* hist = (unsigned*)(smem_raw + CAP * 8);        // 16 KB (fallback)
    __shared__ unsigned csum[TPB_F];
    __shared__ float st[KK], sc[KK];
    __shared__ unsigned s_cnt;
    __shared__ int s_bin;

    const int b   = blockIdx.x;
    const int tid = threadIdx.x;

    unsigned cnt = g_cnt[b];
    if (tid == 0) g_cnt[b] = 0;          // reset for next graph replay

    if (cnt >= KK && cnt <= CAP) {
        // Fast path: copy candidates from global scratch (L2-hot, ~100 elems)
        for (unsigned i = tid; i < cnt; i += TPB_F) {
            cand[i] = g_cand[b * CAP + i];
            cidx[i] = g_cidx[b * CAP + i];
        }
        __syncthreads();
    } else {
        // ---- Exact fallback: 12-bit histogram select over the full row ----
        const float* xrow = x + (size_t)b * NN;
        for (int i = tid; i < NBINS; i += TPB_F) hist[i] = 0;
        if (tid == 0) s_cnt = 0;
        __syncthreads();
        for (int i = tid; i < NN; i += TPB_F) {
            unsigned dg = key_of(xrow[i]) >> 20;
            unsigned peers = __match_any_sync(0xFFFFFFFFu, dg);
            if ((tid & 31) == __ffs(peers) - 1)
                atomicAdd(&hist[dg], (unsigned)__popc(peers));
        }
        __syncthreads();
        {
            unsigned s = 0;
            #pragma unroll
            for (int j = 0; j < BPT; j++) s += hist[tid * BPT + j];
            csum[tid] = s;
            __syncthreads();
            #pragma unroll
            for (int off = 1; off < TPB_F; off <<= 1) {
                unsigned t = (tid + off < TPB_F) ? csum[tid + off] : 0u;
                __syncthreads();
                csum[tid] += t;
                __syncthreads();
            }
        }
        {
            unsigned incl = csum[tid];
            unsigned excl = (tid < TPB_F - 1) ? csum[tid + 1] : 0u;
            if (incl >= KK && excl < KK) {
                unsigned cum = excl;
                #pragma unroll
                for (int j = BPT - 1; j >= 0; j--) {
                    cum += hist[tid * BPT + j];
                    if (cum >= KK) { s_bin = tid * BPT + j; break; }
                }
            }
        }
        __syncthreads();
        const float binlo   = key_to_float((unsigned)s_bin << 20);
        const unsigned thrk = key_of(binlo - 2.0f * EPSf);
        for (int i = tid; i < NN; i += TPB_F) {
            float v = xrow[i];
            if (key_of(v) >= thrk) {
                unsigned p = atomicAdd(&s_cnt, 1u);
                if (p < CAP) { cand[p] = v; cidx[p] = (unsigned)i; }
            }
        }
        __syncthreads();
        cnt = min(s_cnt, (unsigned)CAP);
    }
    const int m = (int)cnt;

    // ---- Rank-select top-32 (descending) among m candidates ----
    for (int i0 = tid; i0 < m; i0 += TPB_F) {
        unsigned kv = key_of(cand[i0]);
        int rank = 0;
        for (int i = 0; i < m; i++) {
            unsigned kw = key_of(cand[i]);
            rank += (kw > kv) || (kw == kv && i < i0);
        }
        if (rank < KK) st[rank] = cand[i0];
    }
    __syncthreads();

    // ---- c_j = 1 - x_m_sum_j (terms exactly 0 or 1 on the fast path ->
    // order-invariant despite atomic collection order) ----
    if (tid < KK) {
        const float tj = st[tid];
        float acc = 0.f;
        for (int i = 0; i < m; i++) {
            float d = cand[i] - tj;
            acc += fmaxf(__fmaf_rn(-d, d, E2f), 0.f) * INV_E2f;
        }
        sc[tid] = 1.0f - acc;
    }
    __syncthreads();

    // ---- Scatter: rewrite the 32-wide segment of each candidate position ----
    for (int w = tid; w < m * 8; w += TPB_F) {
        const int p = w >> 3, q = w & 7, j0 = q * 4;
        const float xv     = cand[p];
        const unsigned idx = cidx[p];
        float d;
        float4 r;
        d = xv - st[j0 + 0]; r.x = fmaxf(__fmaf_rn(fmaxf(__fmaf_rn(-d, d, E2f), 0.f), INV_E2f, sc[j0 + 0]), 0.f);
        d = xv - st[j0 + 1]; r.y = fmaxf(__fmaf_rn(fmaxf(__fmaf_rn(-d, d, E2f), 0.f), INV_E2f, sc[j0 + 1]), 0.f);
        d = xv - st[j0 + 2]; r.z = fmaxf(__fmaf_rn(fmaxf(__fmaf_rn(-d, d, E2f), 0.f), INV_E2f, sc[j0 + 2]), 0.f);
        d = xv - st[j0 + 3]; r.w = fmaxf(__fmaf_rn(fmaxf(__fmaf_rn(-d, d, E2f), 0.f), INV_E2f, sc[j0 + 3]), 0.f);
        float4* dst = (float4*)(out + ((size_t)b * NN + idx) * KK);
        dst[q] = r;
    }
}

// ---------------------------------------------------------------------------
extern "C" void kernel_launch(void* const* d_in, const int* in_sizes, int n_in,
                              void* d_out, int out_size) {
    const float* x = (const float*)d_in[0];
    float* out = (float*)d_out;
    (void)in_sizes; (void)n_in; (void)out_size;   // shapes fixed: (128,16384), k=32

    const int smem_f = CAP * 8 + NBINS * 4;       // 48 KB (cand | cidx | hist)
    cudaFuncSetAttribute(finalize_scatter_kernel,
                         cudaFuncAttributeMaxDynamicSharedMemorySize, smem_f);

    zero_collect_kernel<<<ZGRID, TPB_Z>>>(x, (float4*)out);
    finalize_scatter_kernel<<<BB, TPB_F, smem_f>>>(x, out);
}